// round 10
// baseline (speedup 1.0000x reference)
#include <cuda_runtime.h>
#include <cuda_fp16.h>
#include <cstdint>
#include <cstddef>

#define B_    8
#define S_    1024
#define D_    512
#define H_    8
#define DK_   512
#define HD_   4096

typedef __half fp16;

// ---------------- scratch (device globals; no runtime alloc) ----------------
__device__ fp16 g_sc [(size_t)B_*H_*S_*S_];           // fp16 scaled scores

__device__ fp16 g_q  [(size_t)B_*S_*D_];
__device__ fp16 g_k  [(size_t)B_*S_*D_];
__device__ fp16 g_v  [(size_t)B_*S_*D_];
__device__ fp16 g_wq [(size_t)HD_*D_];
__device__ fp16 g_wk [(size_t)HD_*D_];
__device__ fp16 g_wv [(size_t)HD_*D_];
__device__ fp16 g_wf [(size_t)D_*HD_];

__device__ fp16 g_qh [(size_t)B_*H_*S_*DK_];
__device__ fp16 g_kh [(size_t)B_*H_*S_*DK_];
__device__ fp16 g_vh [(size_t)B_*H_*S_*DK_];          // V heads (z, s, d)
__device__ fp16 g_vt [(size_t)B_*H_*DK_*S_];          // V transposed (z, d, s)
__device__ fp16 g_p  [(size_t)B_*H_*S_*S_];           // softmax probs
__device__ fp16 g_at [(size_t)B_*S_*HD_];             // attention output

// ---------------- helpers ----------------
__device__ __forceinline__ uint32_t smem_u32(const void* p) {
    uint32_t a;
    asm("{ .reg .u64 t; cvta.to.shared.u64 t, %1; cvt.u32.u64 %0, t; }"
        : "=r"(a) : "l"(p));
    return a;
}
__device__ __forceinline__ void cp16(uint32_t s, const void* g) {
    asm volatile("cp.async.cg.shared.global [%0], [%1], 16;" :: "r"(s), "l"(g));
}
__device__ __forceinline__ void cp_commit() { asm volatile("cp.async.commit_group;"); }
template <int N> __device__ __forceinline__ void cp_wait() {
    asm volatile("cp.async.wait_group %0;" :: "n"(N));
}
__device__ __forceinline__ void ldsm4(uint32_t* r, uint32_t a) {
    asm volatile("ldmatrix.sync.aligned.m8n8.x4.shared.b16 {%0,%1,%2,%3}, [%4];"
                 : "=r"(r[0]), "=r"(r[1]), "=r"(r[2]), "=r"(r[3]) : "r"(a));
}
__device__ __forceinline__ void mma16816(float* d, const uint32_t* a, const uint32_t* b) {
    asm volatile("mma.sync.aligned.m16n8k16.row.col.f32.f16.f16.f32 "
                 "{%0,%1,%2,%3}, {%4,%5,%6,%7}, {%8,%9}, {%0,%1,%2,%3};"
                 : "+f"(d[0]), "+f"(d[1]), "+f"(d[2]), "+f"(d[3])
                 : "r"(a[0]), "r"(a[1]), "r"(a[2]), "r"(a[3]),
                   "r"(b[0]), "r"(b[1]));
}
__device__ __forceinline__ uint32_t packh2(float a, float b) {
    const __half2 h = __floats2half2_rn(a, b);
    return *reinterpret_cast<const uint32_t*>(&h);
}

// 128B-row swizzle: 16B chunk c of row r -> chunk c ^ (r & 7)
__device__ __forceinline__ uint32_t swz8(int r, int c) {
    return (uint32_t)(r * 128 + ((c ^ (r & 7)) << 4));
}

// ---------------------------------------------------------------------------
// fp16 HMMA GEMM: C[m,n] = sum_k A[m,k]*B[n,k] (both K-major), fp32 accum.
// CTA 128x128, 4 warps (2m x 2n) of 64x64 tiles, BK=64, 3-stage cp.async.
// EPI_PROJ runs as one launch with grid.z in {0,1,2} selecting operand triple.
// ---------------------------------------------------------------------------
#define NSTAGES 3
#define STAGE_BYTES 32768     // A 16KB + B 16KB (128 rows x 128B)
#define SMEMSZ (NSTAGES * STAGE_BYTES)

enum { EPI_SCORES = 0, EPI_PROJ = 1, EPI_ATT = 2, EPI_FC = 3 };

template <int EPI>
__global__ void __launch_bounds__(128, 2)
gemmh(const fp16* __restrict__ A0, const fp16* __restrict__ B0,
      float* __restrict__ Cf, fp16* __restrict__ Ch,
      const float* __restrict__ resid,
      int K, long long strideA, long long strideB, float scale,
      const fp16* __restrict__ A1, const fp16* __restrict__ A2,
      const fp16* __restrict__ B1, const fp16* __restrict__ B2,
      fp16* __restrict__ Ch1, fp16* __restrict__ Ch2)
{
    extern __shared__ __align__(128) char smem[];
    const uint32_t sb = smem_u32(smem);
    const int tid  = threadIdx.x;
    const int wid  = tid >> 5;
    const int lane = tid & 31;
    const int wm = wid & 1;          // 2 m-groups of 64
    const int wn = wid >> 1;         // 2 n-groups of 64
    const int m0 = blockIdx.y * 128;
    const int n0 = blockIdx.x * 128;
    const int z  = blockIdx.z;

    const fp16* A;
    const fp16* B;
    fp16* Chp = Ch;
    if constexpr (EPI == EPI_PROJ) {
        A   = (z == 0) ? A0 : (z == 1) ? A1 : A2;
        B   = (z == 0) ? B0 : (z == 1) ? B1 : B2;
        Chp = (z == 0) ? Ch : (z == 1) ? Ch1 : Ch2;
    } else {
        A = A0 + (size_t)z * strideA;
        B = B0 + (size_t)z * strideB;
    }

    const int NK = K >> 6;

    auto load_iter = [&](int t, int stage) {
        const uint32_t sA = sb + (uint32_t)stage * STAGE_BYTES;
        const uint32_t sB = sA + 16384;
        const int kb = t * 64;
#pragma unroll
        for (int i = 0; i < 8; i++) {
            const int chunk = i * 128 + tid;   // 1024 chunks: 128 rows x 8
            const int r = chunk >> 3, c = chunk & 7;
            cp16(sA + swz8(r, c), A + (size_t)(m0 + r) * K + kb + c * 8);
        }
#pragma unroll
        for (int i = 0; i < 8; i++) {
            const int chunk = i * 128 + tid;
            const int r = chunk >> 3, c = chunk & 7;
            cp16(sB + swz8(r, c), B + (size_t)(n0 + r) * K + kb + c * 8);
        }
    };

    float acc[4][8][4];
#pragma unroll
    for (int a = 0; a < 4; a++)
#pragma unroll
        for (int b = 0; b < 8; b++)
#pragma unroll
            for (int c = 0; c < 4; c++) acc[a][b][c] = 0.0f;

    load_iter(0, 0); cp_commit();
    load_iter(1, 1); cp_commit();

    const int g  = lane >> 3;              // ldsm4 address-group id
    const int gl = lane & 7;

    for (int i = 0; i < NK; i++) {
        cp_wait<1>();
        __syncthreads();

        // issue next-stage global loads FIRST so DRAM latency overlaps math
        const int j = i + 2;
        if (j < NK) load_iter(j, j % 3);
        cp_commit();

        const uint32_t sA = sb + (uint32_t)(i % 3) * STAGE_BYTES;
        const uint32_t sB = sA + 16384;

#pragma unroll
        for (int q = 0; q < 4; q++) {
            // hoist ALL fragment loads for this q-block (8 back-to-back ldsm4)
            uint32_t bfr[8][2];
#pragma unroll
            for (int ni = 0; ni < 8; ni += 2) {
                uint32_t r4[4];
                const int nr = wn * 64 + ni * 8 + ((g >> 1) << 3) + gl;
                const int c  = q * 2 + (g & 1);
                ldsm4(r4, sB + swz8(nr, c));
                bfr[ni][0]     = r4[0]; bfr[ni][1]     = r4[1];
                bfr[ni + 1][0] = r4[2]; bfr[ni + 1][1] = r4[3];
            }
            uint32_t afr[4][4];
#pragma unroll
            for (int mi = 0; mi < 4; mi++) {
                const int mr = wm * 64 + mi * 16 + (lane & 15);
                const int c  = q * 2 + (lane >> 4);
                ldsm4(afr[mi], sA + swz8(mr, c));
            }
#pragma unroll
            for (int mi = 0; mi < 4; mi++)
#pragma unroll
                for (int ni = 0; ni < 8; ni++)
                    mma16816(acc[mi][ni], afr[mi], bfr[ni]);
        }
    }

    // ---------------- epilogue ----------------
    const int l4 = lane >> 2;            // row within 8
    const int l2 = (lane & 3) * 2;       // col pair
#pragma unroll
    for (int mi = 0; mi < 4; mi++) {
#pragma unroll
        for (int h2 = 0; h2 < 2; h2++) {
            const int row = m0 + wm * 64 + mi * 16 + l4 + h2 * 8;
#pragma unroll
            for (int ni = 0; ni < 8; ni++) {
                const int col = n0 + wn * 64 + ni * 8 + l2;
                const float v0 = acc[mi][ni][2 * h2 + 0];
                const float v1 = acc[mi][ni][2 * h2 + 1];

                if constexpr (EPI == EPI_SCORES) {
                    fp16* p = Ch + (size_t)z * S_ * S_ + (size_t)row * S_ + col;
                    *reinterpret_cast<uint32_t*>(p) = packh2(v0 * scale, v1 * scale);
                } else if constexpr (EPI == EPI_FC) {
                    const size_t base = (size_t)row * D_ + col;
                    const float2 rv = *reinterpret_cast<const float2*>(resid + base);
                    *reinterpret_cast<float2*>(Cf + base) =
                        make_float2(v0 + rv.x, v1 + rv.y);
                } else if constexpr (EPI == EPI_PROJ) {
                    const int b = row >> 10, s = row & (S_ - 1);
                    const int hh = col >> 9, d = col & (DK_ - 1);
                    const size_t base = (((size_t)(b * H_ + hh)) * S_ + s) * DK_ + d;
                    *reinterpret_cast<uint32_t*>(Chp + base) = packh2(v0, v1);
                } else { // EPI_ATT
                    const int b = z >> 3, hh = z & (H_ - 1);
                    const size_t base = ((size_t)(b * S_ + row)) * HD_ + hh * DK_ + col;
                    *reinterpret_cast<uint32_t*>(Ch + base) = packh2(v0, v1);
                }
            }
        }
    }
}

// ---------------- fp32 -> fp16 convert: all 7 tensors in one launch ---------
__global__ void __launch_bounds__(256) conv7_k(
    const float* __restrict__ s0, const float* __restrict__ s1,
    const float* __restrict__ s2, const float* __restrict__ s3,
    const float* __restrict__ s4, const float* __restrict__ s5,
    const float* __restrict__ s6,
    fp16* __restrict__ h0, fp16* __restrict__ h1, fp16* __restrict__ h2,
    fp16* __restrict__ h3, fp16* __restrict__ h4, fp16* __restrict__ h5,
    fp16* __restrict__ h6,
    int n_big, int n_small)
{
    const int zz = blockIdx.z;
    const float* s; fp16* h; int n;
    switch (zz) {
        case 0: s = s0; h = h0; n = n_big;   break;
        case 1: s = s1; h = h1; n = n_big;   break;
        case 2: s = s2; h = h2; n = n_big;   break;
        case 3: s = s3; h = h3; n = n_small; break;
        case 4: s = s4; h = h4; n = n_small; break;
        case 5: s = s5; h = h5; n = n_small; break;
        default: s = s6; h = h6; n = n_small; break;
    }
    const int i = (blockIdx.x * 256 + threadIdx.x) * 4;
    if (i >= n) return;
    float4 v = *reinterpret_cast<const float4*>(s + i);
    *reinterpret_cast<uint2*>(h + i) = make_uint2(packh2(v.x, v.y), packh2(v.z, v.w));
}

// ---------------- V transpose: (z, s, d) -> (z, d, s), 64x64 tiles ----------
__global__ void __launch_bounds__(256) transp_k(const fp16* __restrict__ in,
                                                fp16* __restrict__ out)
{
    __shared__ fp16 t[64][72];
    const int zz = blockIdx.z;
    const int d0 = blockIdx.x * 64, s0 = blockIdx.y * 64;
    const int tid = threadIdx.x;
    const int rs = tid >> 2, cb = (tid & 3) * 16;

    const fp16* src = in + ((size_t)zz * S_ + s0 + rs) * DK_ + d0 + cb;
    *reinterpret_cast<uint4*>(&t[rs][cb])     = reinterpret_cast<const uint4*>(src)[0];
    *reinterpret_cast<uint4*>(&t[rs][cb + 8]) = reinterpret_cast<const uint4*>(src)[1];
    __syncthreads();

    fp16 buf[16];
#pragma unroll
    for (int j = 0; j < 16; j++) buf[j] = t[cb + j][rs];
    fp16* dst = out + ((size_t)zz * DK_ + d0 + rs) * S_ + s0 + cb;
    reinterpret_cast<uint4*>(dst)[0] = *reinterpret_cast<uint4*>(&buf[0]);
    reinterpret_cast<uint4*>(dst)[1] = *reinterpret_cast<uint4*>(&buf[8]);
}

// ---------------- row softmax (len 1024, fp16 in) -> fp16 probs -------------
__global__ void __launch_bounds__(256) softmax_k(const fp16* __restrict__ sc,
                                                 fp16* __restrict__ ph)
{
    const size_t row = blockIdx.x;
    const uint2 raw = *(reinterpret_cast<const uint2*>(sc) + row * 256 + threadIdx.x);
    const __half2 h01 = *reinterpret_cast<const __half2*>(&raw.x);
    const __half2 h23 = *reinterpret_cast<const __half2*>(&raw.y);
    const float2 f01 = __half22float2(h01);
    const float2 f23 = __half22float2(h23);
    float4 v = make_float4(f01.x, f01.y, f23.x, f23.y);

    __shared__ float red[8];

    float m = fmaxf(fmaxf(v.x, v.y), fmaxf(v.z, v.w));
#pragma unroll
    for (int o = 16; o; o >>= 1) m = fmaxf(m, __shfl_xor_sync(0xffffffffu, m, o));
    if ((threadIdx.x & 31) == 0) red[threadIdx.x >> 5] = m;
    __syncthreads();
    m = red[0];
#pragma unroll
    for (int i = 1; i < 8; i++) m = fmaxf(m, red[i]);

    v.x = expf(v.x - m); v.y = expf(v.y - m);
    v.z = expf(v.z - m); v.w = expf(v.w - m);

    float s = v.x + v.y + v.z + v.w;
#pragma unroll
    for (int o = 16; o; o >>= 1) s += __shfl_xor_sync(0xffffffffu, s, o);
    __syncthreads();
    if ((threadIdx.x & 31) == 0) red[threadIdx.x >> 5] = s;
    __syncthreads();
    s = 0.0f;
#pragma unroll
    for (int i = 0; i < 8; i++) s += red[i];

    const float inv = 1.0f / s;
    const size_t base = row * 1024 + threadIdx.x * 4;
    *reinterpret_cast<uint2*>(ph + base) =
        make_uint2(packh2(v.x * inv, v.y * inv), packh2(v.z * inv, v.w * inv));
}

// ---------------- LayerNorm (len 512), in-place ----------------
__global__ void __launch_bounds__(256) ln_k(float* __restrict__ out,
                                            const float* __restrict__ gamma,
                                            const float* __restrict__ beta)
{
    const size_t row = blockIdx.x;
    float2* p = reinterpret_cast<float2*>(out) + row * 256 + threadIdx.x;
    float2 v = *p;

    float s  = v.x + v.y;
    float ss = v.x * v.x + v.y * v.y;

    __shared__ float r1[8], r2[8];
#pragma unroll
    for (int o = 16; o; o >>= 1) {
        s  += __shfl_xor_sync(0xffffffffu, s, o);
        ss += __shfl_xor_sync(0xffffffffu, ss, o);
    }
    if ((threadIdx.x & 31) == 0) { r1[threadIdx.x >> 5] = s; r2[threadIdx.x >> 5] = ss; }
    __syncthreads();
    s = 0.0f; ss = 0.0f;
#pragma unroll
    for (int i = 0; i < 8; i++) { s += r1[i]; ss += r2[i]; }

    const float mu  = s * (1.0f / 512.0f);
    const float var = ss * (1.0f / 512.0f) - mu * mu;
    const float inv = rsqrtf(var + 1e-6f);

    const int c = threadIdx.x * 2;
    v.x = (v.x - mu) * inv * gamma[c + 0] + beta[c + 0];
    v.y = (v.y - mu) * inv * gamma[c + 1] + beta[c + 1];
    *p = v;
}

// ---------------------------------------------------------------------------
extern "C" void kernel_launch(void* const* d_in, const int* in_sizes, int n_in,
                              void* d_out, int out_size)
{
    const float* in_q  = (const float*)d_in[0];
    const float* in_k  = (const float*)d_in[1];
    const float* in_v  = (const float*)d_in[2];
    const float* w_q   = (const float*)d_in[3];
    const float* w_k   = (const float*)d_in[4];
    const float* w_v   = (const float*)d_in[5];
    const float* w_fc  = (const float*)d_in[6];
    const float* gamma = (const float*)d_in[7];
    const float* beta  = (const float*)d_in[8];
    float* out = (float*)d_out;

    cudaFuncSetAttribute(gemmh<EPI_SCORES>, cudaFuncAttributeMaxDynamicSharedMemorySize, SMEMSZ);
    cudaFuncSetAttribute(gemmh<EPI_PROJ>,   cudaFuncAttributeMaxDynamicSharedMemorySize, SMEMSZ);
    cudaFuncSetAttribute(gemmh<EPI_ATT>,    cudaFuncAttributeMaxDynamicSharedMemorySize, SMEMSZ);
    cudaFuncSetAttribute(gemmh<EPI_FC>,     cudaFuncAttributeMaxDynamicSharedMemorySize, SMEMSZ);

    fp16 *qh, *kh, *vh, *wq, *wk, *wv, *wf;
    fp16 *qhh, *khh, *vhh, *vt, *ph, *at, *sc;
    cudaGetSymbolAddress((void**)&sc, g_sc);
    cudaGetSymbolAddress((void**)&qh, g_q);   cudaGetSymbolAddress((void**)&kh, g_k);
    cudaGetSymbolAddress((void**)&vh, g_v);
    cudaGetSymbolAddress((void**)&wq, g_wq);  cudaGetSymbolAddress((void**)&wk, g_wk);
    cudaGetSymbolAddress((void**)&wv, g_wv);  cudaGetSymbolAddress((void**)&wf, g_wf);
    cudaGetSymbolAddress((void**)&qhh, g_qh); cudaGetSymbolAddress((void**)&khh, g_kh);
    cudaGetSymbolAddress((void**)&vhh, g_vh); cudaGetSymbolAddress((void**)&vt, g_vt);
    cudaGetSymbolAddress((void**)&ph, g_p);   cudaGetSymbolAddress((void**)&at, g_at);

    const int NX = B_ * S_ * D_;     // 4M
    const int NW = HD_ * D_;         // 2M
    conv7_k<<<dim3(NX / 1024, 1, 7), 256>>>(in_q, in_k, in_v, w_q, w_k, w_v, w_fc,
                                            qh, kh, vh, wq, wk, wv, wf, NX, NW);

    const float SCALE = 0.044194173824159216f;   // 1/sqrt(512)

    // 1) projections (M=8192, N=4096, K=512), all three in ONE launch (z=0..2)
    const dim3 gp(HD_ / 128, (B_ * S_) / 128, 3);
    gemmh<EPI_PROJ><<<gp, 128, SMEMSZ>>>(qh, wq, nullptr, qhh, nullptr, D_, 0, 0, 1.0f,
                                         kh, vh, wk, wv, khh, vhh);

    // 1b) V transpose: (z,s,d) -> (z,d,s) so PV stays row.col
    transp_k<<<dim3(DK_ / 64, S_ / 64, B_ * H_), 256>>>(vhh, vt);

    // 2) scores (per z: M=N=1024, K=512), scaled, fp16 out
    const dim3 gs(S_ / 128, S_ / 128, B_ * H_);
    gemmh<EPI_SCORES><<<gs, 128, SMEMSZ>>>(qhh, khh, nullptr, sc, nullptr,
                                           DK_, (long long)S_ * DK_, (long long)S_ * DK_, SCALE,
                                           nullptr, nullptr, nullptr, nullptr, nullptr, nullptr);

    // 3) softmax -> fp16 P
    softmax_k<<<B_ * H_ * S_, 256>>>(sc, ph);

    // 4) P @ V (per z: M=1024, N=512, K=1024; B = V^T)
    const dim3 gv(DK_ / 128, S_ / 128, B_ * H_);
    gemmh<EPI_ATT><<<gv, 128, SMEMSZ>>>(ph, vt, nullptr, at, nullptr,
                                        S_, (long long)S_ * S_, (long long)DK_ * S_, 1.0f,
                                        nullptr, nullptr, nullptr, nullptr, nullptr, nullptr);

    // 5) fc + residual (M=8192, N=512, K=4096)
    const dim3 gf(D_ / 128, (B_ * S_) / 128, 1);
    gemmh<EPI_FC><<<gf, 128, SMEMSZ>>>(at, wf, out, nullptr, in_q, HD_, 0, 0, 1.0f,
                                       nullptr, nullptr, nullptr, nullptr, nullptr, nullptr);

    // 6) LayerNorm
    ln_k<<<B_ * S_, 256>>>(out, gamma, beta);
}

// round 14
// speedup vs baseline: 1.0475x; 1.0475x over previous
#include <cuda_runtime.h>
#include <cuda_fp16.h>
#include <cstdint>
#include <cstddef>

#define B_    8
#define S_    1024
#define D_    512
#define H_    8
#define DK_   512
#define HD_   4096

typedef __half fp16;

// ---------------- scratch (device globals; no runtime alloc) ----------------
__device__ fp16 g_sc [(size_t)B_*H_*S_*S_];           // fp16 scaled scores

__device__ fp16 g_q  [(size_t)B_*S_*D_];
__device__ fp16 g_k  [(size_t)B_*S_*D_];
__device__ fp16 g_v  [(size_t)B_*S_*D_];
__device__ fp16 g_wq [(size_t)HD_*D_];
__device__ fp16 g_wk [(size_t)HD_*D_];
__device__ fp16 g_wv [(size_t)HD_*D_];
__device__ fp16 g_wf [(size_t)D_*HD_];

__device__ fp16 g_qh [(size_t)B_*H_*S_*DK_];
__device__ fp16 g_kh [(size_t)B_*H_*S_*DK_];
__device__ fp16 g_vh [(size_t)B_*H_*S_*DK_];          // V heads (z, s, d)
__device__ fp16 g_vt [(size_t)B_*H_*DK_*S_];          // V transposed (z, d, s)
__device__ fp16 g_p  [(size_t)B_*H_*S_*S_];           // softmax probs
__device__ fp16 g_at [(size_t)B_*S_*HD_];             // attention output

// ---------------- helpers ----------------
__device__ __forceinline__ uint32_t smem_u32(const void* p) {
    uint32_t a;
    asm("{ .reg .u64 t; cvta.to.shared.u64 t, %1; cvt.u32.u64 %0, t; }"
        : "=r"(a) : "l"(p));
    return a;
}
__device__ __forceinline__ void cp16(uint32_t s, const void* g) {
    asm volatile("cp.async.cg.shared.global [%0], [%1], 16;" :: "r"(s), "l"(g));
}
__device__ __forceinline__ void cp_commit() { asm volatile("cp.async.commit_group;"); }
template <int N> __device__ __forceinline__ void cp_wait() {
    asm volatile("cp.async.wait_group %0;" :: "n"(N));
}
__device__ __forceinline__ void ldsm4(uint32_t* r, uint32_t a) {
    asm volatile("ldmatrix.sync.aligned.m8n8.x4.shared.b16 {%0,%1,%2,%3}, [%4];"
                 : "=r"(r[0]), "=r"(r[1]), "=r"(r[2]), "=r"(r[3]) : "r"(a));
}
// fp32-accumulate HMMA
__device__ __forceinline__ void mma16816(float* d, const uint32_t* a, const uint32_t* b) {
    asm volatile("mma.sync.aligned.m16n8k16.row.col.f32.f16.f16.f32 "
                 "{%0,%1,%2,%3}, {%4,%5,%6,%7}, {%8,%9}, {%0,%1,%2,%3};"
                 : "+f"(d[0]), "+f"(d[1]), "+f"(d[2]), "+f"(d[3])
                 : "r"(a[0]), "r"(a[1]), "r"(a[2]), "r"(a[3]),
                   "r"(b[0]), "r"(b[1]));
}
// fp16-accumulate HMMA (2 output regs = 4 halves)
__device__ __forceinline__ void mma16816h(uint32_t* d, const uint32_t* a, const uint32_t* b) {
    asm volatile("mma.sync.aligned.m16n8k16.row.col.f16.f16.f16.f16 "
                 "{%0,%1}, {%2,%3,%4,%5}, {%6,%7}, {%0,%1};"
                 : "+r"(d[0]), "+r"(d[1])
                 : "r"(a[0]), "r"(a[1]), "r"(a[2]), "r"(a[3]),
                   "r"(b[0]), "r"(b[1]));
}
__device__ __forceinline__ uint32_t packh2(float a, float b) {
    const __half2 h = __floats2half2_rn(a, b);
    return *reinterpret_cast<const uint32_t*>(&h);
}

// 128B-row swizzle: 16B chunk c of row r -> chunk c ^ (r & 7)
__device__ __forceinline__ uint32_t swz8(int r, int c) {
    return (uint32_t)(r * 128 + ((c ^ (r & 7)) << 4));
}

enum { EPI_SCORES = 0, EPI_PROJ = 1, EPI_ATT = 2 };

// ---------------------------------------------------------------------------
// fp16-accum HMMA GEMM (proj / scores / PV). CTA 128x128, 4 warps of 64x64,
// BK=64, 2-stage cp.async, 3 CTAs/SM (64KB smem, ~150 regs).
// ---------------------------------------------------------------------------
#define STAGE_BYTES 32768     // A 16KB + B 16KB (128 rows x 128B)
#define SMEMSZ16 (2 * STAGE_BYTES)

template <int EPI>
__global__ void __launch_bounds__(128, 3)
gemmh16(const fp16* __restrict__ A0, const fp16* __restrict__ B0,
        fp16* __restrict__ Ch,
        int K, long long strideA, long long strideB, float scale,
        const fp16* __restrict__ A1, const fp16* __restrict__ A2,
        const fp16* __restrict__ B1, const fp16* __restrict__ B2,
        fp16* __restrict__ Ch1, fp16* __restrict__ Ch2)
{
    extern __shared__ __align__(128) char smem[];
    const uint32_t sb = smem_u32(smem);
    const int tid  = threadIdx.x;
    const int wid  = tid >> 5;
    const int lane = tid & 31;
    const int wm = wid & 1;
    const int wn = wid >> 1;
    const int m0 = blockIdx.y * 128;
    const int n0 = blockIdx.x * 128;
    const int z  = blockIdx.z;

    const fp16* A;
    const fp16* B;
    fp16* Chp = Ch;
    if constexpr (EPI == EPI_PROJ) {
        A   = (z == 0) ? A0 : (z == 1) ? A1 : A2;
        B   = (z == 0) ? B0 : (z == 1) ? B1 : B2;
        Chp = (z == 0) ? Ch : (z == 1) ? Ch1 : Ch2;
    } else {
        A = A0 + (size_t)z * strideA;
        B = B0 + (size_t)z * strideB;
    }

    const int NK = K >> 6;

    auto load_iter = [&](int t, int stage) {
        const uint32_t sA = sb + (uint32_t)stage * STAGE_BYTES;
        const uint32_t sB = sA + 16384;
        const int kb = t * 64;
#pragma unroll
        for (int i = 0; i < 8; i++) {
            const int chunk = i * 128 + tid;
            const int r = chunk >> 3, c = chunk & 7;
            cp16(sA + swz8(r, c), A + (size_t)(m0 + r) * K + kb + c * 8);
        }
#pragma unroll
        for (int i = 0; i < 8; i++) {
            const int chunk = i * 128 + tid;
            const int r = chunk >> 3, c = chunk & 7;
            cp16(sB + swz8(r, c), B + (size_t)(n0 + r) * K + kb + c * 8);
        }
    };

    uint32_t acc[4][8][2];
#pragma unroll
    for (int a = 0; a < 4; a++)
#pragma unroll
        for (int b = 0; b < 8; b++) { acc[a][b][0] = 0u; acc[a][b][1] = 0u; }

    load_iter(0, 0); cp_commit();

    const int g  = lane >> 3;
    const int gl = lane & 7;

    for (int i = 0; i < NK; i++) {
        cp_wait<0>();
        __syncthreads();
        // prefetch next stage; its last readers finished iter i-1 (barrier above)
        if (i + 1 < NK) { load_iter(i + 1, (i + 1) & 1); cp_commit(); }

        const uint32_t sA = sb + (uint32_t)(i & 1) * STAGE_BYTES;
        const uint32_t sB = sA + 16384;

#pragma unroll
        for (int q = 0; q < 4; q++) {
            uint32_t bfr[8][2];
#pragma unroll
            for (int ni = 0; ni < 8; ni += 2) {
                uint32_t r4[4];
                const int nr = wn * 64 + ni * 8 + ((g >> 1) << 3) + gl;
                const int c  = q * 2 + (g & 1);
                ldsm4(r4, sB + swz8(nr, c));
                bfr[ni][0]     = r4[0]; bfr[ni][1]     = r4[1];
                bfr[ni + 1][0] = r4[2]; bfr[ni + 1][1] = r4[3];
            }
#pragma unroll
            for (int mi = 0; mi < 4; mi++) {
                uint32_t afr[4];
                const int mr = wm * 64 + mi * 16 + (lane & 15);
                const int c  = q * 2 + (lane >> 4);
                ldsm4(afr, sA + swz8(mr, c));
#pragma unroll
                for (int ni = 0; ni < 8; ni++)
                    mma16816h(acc[mi][ni], afr, bfr[ni]);
            }
        }
    }

    // ---------------- epilogue (acc words are 2 packed halves, cols l2,l2+1) --
    const int l4 = lane >> 2;
    const int l2 = (lane & 3) * 2;
    const __half2 s2 = __float2half2_rn(scale);
#pragma unroll
    for (int mi = 0; mi < 4; mi++) {
#pragma unroll
        for (int h2 = 0; h2 < 2; h2++) {
            const int row = m0 + wm * 64 + mi * 16 + l4 + h2 * 8;
#pragma unroll
            for (int ni = 0; ni < 8; ni++) {
                const int col = n0 + wn * 64 + ni * 8 + l2;
                uint32_t w = acc[mi][ni][h2];

                if constexpr (EPI == EPI_SCORES) {
                    __half2 hv = __hmul2(*reinterpret_cast<__half2*>(&w), s2);
                    fp16* p = Ch + (size_t)z * S_ * S_ + (size_t)row * S_ + col;
                    *reinterpret_cast<uint32_t*>(p) = *reinterpret_cast<uint32_t*>(&hv);
                } else if constexpr (EPI == EPI_PROJ) {
                    const int b = row >> 10, s = row & (S_ - 1);
                    const int hh = col >> 9, d = col & (DK_ - 1);
                    const size_t base = (((size_t)(b * H_ + hh)) * S_ + s) * DK_ + d;
                    *reinterpret_cast<uint32_t*>(Chp + base) = w;
                } else { // EPI_ATT
                    const int b = z >> 3, hh = z & (H_ - 1);
                    const size_t base = ((size_t)(b * S_ + row)) * HD_ + hh * DK_ + col;
                    *reinterpret_cast<uint32_t*>(Ch + base) = w;
                }
            }
        }
    }
}

// ---------------------------------------------------------------------------
// fp32-accum HMMA GEMM for fc (+residual). CTA 128x128, 4 warps, BK=64,
// 3-stage cp.async, 2 CTAs/SM.
// ---------------------------------------------------------------------------
#define SMEMSZF (3 * STAGE_BYTES)

__global__ void __launch_bounds__(128, 2)
gemmfc(const fp16* __restrict__ A, const fp16* __restrict__ B,
       float* __restrict__ Cf, const float* __restrict__ resid, int K)
{
    extern __shared__ __align__(128) char smem[];
    const uint32_t sb = smem_u32(smem);
    const int tid  = threadIdx.x;
    const int wid  = tid >> 5;
    const int lane = tid & 31;
    const int wm = wid & 1;
    const int wn = wid >> 1;
    const int m0 = blockIdx.y * 128;
    const int n0 = blockIdx.x * 128;

    const int NK = K >> 6;

    auto load_iter = [&](int t, int stage) {
        const uint32_t sA = sb + (uint32_t)stage * STAGE_BYTES;
        const uint32_t sB = sA + 16384;
        const int kb = t * 64;
#pragma unroll
        for (int i = 0; i < 8; i++) {
            const int chunk = i * 128 + tid;
            const int r = chunk >> 3, c = chunk & 7;
            cp16(sA + swz8(r, c), A + (size_t)(m0 + r) * K + kb + c * 8);
        }
#pragma unroll
        for (int i = 0; i < 8; i++) {
            const int chunk = i * 128 + tid;
            const int r = chunk >> 3, c = chunk & 7;
            cp16(sB + swz8(r, c), B + (size_t)(n0 + r) * K + kb + c * 8);
        }
    };

    float acc[4][8][4];
#pragma unroll
    for (int a = 0; a < 4; a++)
#pragma unroll
        for (int b = 0; b < 8; b++)
#pragma unroll
            for (int c = 0; c < 4; c++) acc[a][b][c] = 0.0f;

    load_iter(0, 0); cp_commit();
    load_iter(1, 1); cp_commit();

    const int g  = lane >> 3;
    const int gl = lane & 7;

    for (int i = 0; i < NK; i++) {
        cp_wait<1>();
        __syncthreads();
        const int j = i + 2;
        if (j < NK) load_iter(j, j % 3);
        cp_commit();

        const uint32_t sA = sb + (uint32_t)(i % 3) * STAGE_BYTES;
        const uint32_t sB = sA + 16384;

#pragma unroll
        for (int q = 0; q < 4; q++) {
            uint32_t bfr[8][2];
#pragma unroll
            for (int ni = 0; ni < 8; ni += 2) {
                uint32_t r4[4];
                const int nr = wn * 64 + ni * 8 + ((g >> 1) << 3) + gl;
                const int c  = q * 2 + (g & 1);
                ldsm4(r4, sB + swz8(nr, c));
                bfr[ni][0]     = r4[0]; bfr[ni][1]     = r4[1];
                bfr[ni + 1][0] = r4[2]; bfr[ni + 1][1] = r4[3];
            }
#pragma unroll
            for (int mi = 0; mi < 4; mi++) {
                uint32_t afr[4];
                const int mr = wm * 64 + mi * 16 + (lane & 15);
                const int c  = q * 2 + (lane >> 4);
                ldsm4(afr, sA + swz8(mr, c));
#pragma unroll
                for (int ni = 0; ni < 8; ni++)
                    mma16816(acc[mi][ni], afr, bfr[ni]);
            }
        }
    }

    const int l4 = lane >> 2;
    const int l2 = (lane & 3) * 2;
#pragma unroll
    for (int mi = 0; mi < 4; mi++) {
#pragma unroll
        for (int h2 = 0; h2 < 2; h2++) {
            const int row = m0 + wm * 64 + mi * 16 + l4 + h2 * 8;
#pragma unroll
            for (int ni = 0; ni < 8; ni++) {
                const int col = n0 + wn * 64 + ni * 8 + l2;
                const size_t base = (size_t)row * D_ + col;
                const float2 rv = *reinterpret_cast<const float2*>(resid + base);
                *reinterpret_cast<float2*>(Cf + base) =
                    make_float2(acc[mi][ni][2 * h2 + 0] + rv.x,
                                acc[mi][ni][2 * h2 + 1] + rv.y);
            }
        }
    }
}

// ---------------- fp32 -> fp16 convert: all 7 tensors in one launch ---------
__global__ void __launch_bounds__(256) conv7_k(
    const float* __restrict__ s0, const float* __restrict__ s1,
    const float* __restrict__ s2, const float* __restrict__ s3,
    const float* __restrict__ s4, const float* __restrict__ s5,
    const float* __restrict__ s6,
    fp16* __restrict__ h0, fp16* __restrict__ h1, fp16* __restrict__ h2,
    fp16* __restrict__ h3, fp16* __restrict__ h4, fp16* __restrict__ h5,
    fp16* __restrict__ h6,
    int n_big, int n_small)
{
    const int zz = blockIdx.z;
    const float* s; fp16* h; int n;
    switch (zz) {
        case 0: s = s0; h = h0; n = n_big;   break;
        case 1: s = s1; h = h1; n = n_big;   break;
        case 2: s = s2; h = h2; n = n_big;   break;
        case 3: s = s3; h = h3; n = n_small; break;
        case 4: s = s4; h = h4; n = n_small; break;
        case 5: s = s5; h = h5; n = n_small; break;
        default: s = s6; h = h6; n = n_small; break;
    }
    const int i = (blockIdx.x * 256 + threadIdx.x) * 4;
    if (i >= n) return;
    float4 v = *reinterpret_cast<const float4*>(s + i);
    *reinterpret_cast<uint2*>(h + i) = make_uint2(packh2(v.x, v.y), packh2(v.z, v.w));
}

// ---------------- V transpose: (z, s, d) -> (z, d, s), 64x64 tiles ----------
__global__ void __launch_bounds__(256) transp_k(const fp16* __restrict__ in,
                                                fp16* __restrict__ out)
{
    __shared__ fp16 t[64][72];
    const int zz = blockIdx.z;
    const int d0 = blockIdx.x * 64, s0 = blockIdx.y * 64;
    const int tid = threadIdx.x;
    const int rs = tid >> 2, cb = (tid & 3) * 16;

    const fp16* src = in + ((size_t)zz * S_ + s0 + rs) * DK_ + d0 + cb;
    *reinterpret_cast<uint4*>(&t[rs][cb])     = reinterpret_cast<const uint4*>(src)[0];
    *reinterpret_cast<uint4*>(&t[rs][cb + 8]) = reinterpret_cast<const uint4*>(src)[1];
    __syncthreads();

    fp16 buf[16];
#pragma unroll
    for (int j = 0; j < 16; j++) buf[j] = t[cb + j][rs];
    fp16* dst = out + ((size_t)zz * DK_ + d0 + rs) * S_ + s0 + cb;
    reinterpret_cast<uint4*>(dst)[0] = *reinterpret_cast<uint4*>(&buf[0]);
    reinterpret_cast<uint4*>(dst)[1] = *reinterpret_cast<uint4*>(&buf[8]);
}

// ---------------- row softmax (len 1024, fp16 in) -> fp16 probs -------------
__global__ void __launch_bounds__(256) softmax_k(const fp16* __restrict__ sc,
                                                 fp16* __restrict__ ph)
{
    const size_t row = blockIdx.x;
    const uint2 raw = *(reinterpret_cast<const uint2*>(sc) + row * 256 + threadIdx.x);
    const __half2 h01 = *reinterpret_cast<const __half2*>(&raw.x);
    const __half2 h23 = *reinterpret_cast<const __half2*>(&raw.y);
    const float2 f01 = __half22float2(h01);
    const float2 f23 = __half22float2(h23);
    float4 v = make_float4(f01.x, f01.y, f23.x, f23.y);

    __shared__ float red[8];

    float m = fmaxf(fmaxf(v.x, v.y), fmaxf(v.z, v.w));
#pragma unroll
    for (int o = 16; o; o >>= 1) m = fmaxf(m, __shfl_xor_sync(0xffffffffu, m, o));
    if ((threadIdx.x & 31) == 0) red[threadIdx.x >> 5] = m;
    __syncthreads();
    m = red[0];
#pragma unroll
    for (int i = 1; i < 8; i++) m = fmaxf(m, red[i]);

    v.x = expf(v.x - m); v.y = expf(v.y - m);
    v.z = expf(v.z - m); v.w = expf(v.w - m);

    float s = v.x + v.y + v.z + v.w;
#pragma unroll
    for (int o = 16; o; o >>= 1) s += __shfl_xor_sync(0xffffffffu, s, o);
    __syncthreads();
    if ((threadIdx.x & 31) == 0) red[threadIdx.x >> 5] = s;
    __syncthreads();
    s = 0.0f;
#pragma unroll
    for (int i = 0; i < 8; i++) s += red[i];

    const float inv = 1.0f / s;
    const size_t base = row * 1024 + threadIdx.x * 4;
    *reinterpret_cast<uint2*>(ph + base) =
        make_uint2(packh2(v.x * inv, v.y * inv), packh2(v.z * inv, v.w * inv));
}

// ---------------- LayerNorm (len 512), in-place ----------------
__global__ void __launch_bounds__(256) ln_k(float* __restrict__ out,
                                            const float* __restrict__ gamma,
                                            const float* __restrict__ beta)
{
    const size_t row = blockIdx.x;
    float2* p = reinterpret_cast<float2*>(out) + row * 256 + threadIdx.x;
    float2 v = *p;

    float s  = v.x + v.y;
    float ss = v.x * v.x + v.y * v.y;

    __shared__ float r1[8], r2[8];
#pragma unroll
    for (int o = 16; o; o >>= 1) {
        s  += __shfl_xor_sync(0xffffffffu, s, o);
        ss += __shfl_xor_sync(0xffffffffu, ss, o);
    }
    if ((threadIdx.x & 31) == 0) { r1[threadIdx.x >> 5] = s; r2[threadIdx.x >> 5] = ss; }
    __syncthreads();
    s = 0.0f; ss = 0.0f;
#pragma unroll
    for (int i = 0; i < 8; i++) { s += r1[i]; ss += r2[i]; }

    const float mu  = s * (1.0f / 512.0f);
    const float var = ss * (1.0f / 512.0f) - mu * mu;
    const float inv = rsqrtf(var + 1e-6f);

    const int c = threadIdx.x * 2;
    v.x = (v.x - mu) * inv * gamma[c + 0] + beta[c + 0];
    v.y = (v.y - mu) * inv * gamma[c + 1] + beta[c + 1];
    *p = v;
}

// ---------------------------------------------------------------------------
extern "C" void kernel_launch(void* const* d_in, const int* in_sizes, int n_in,
                              void* d_out, int out_size)
{
    const float* in_q  = (const float*)d_in[0];
    const float* in_k  = (const float*)d_in[1];
    const float* in_v  = (const float*)d_in[2];
    const float* w_q   = (const float*)d_in[3];
    const float* w_k   = (const float*)d_in[4];
    const float* w_v   = (const float*)d_in[5];
    const float* w_fc  = (const float*)d_in[6];
    const float* gamma = (const float*)d_in[7];
    const float* beta  = (const float*)d_in[8];
    float* out = (float*)d_out;

    cudaFuncSetAttribute(gemmh16<EPI_SCORES>, cudaFuncAttributeMaxDynamicSharedMemorySize, SMEMSZ16);
    cudaFuncSetAttribute(gemmh16<EPI_PROJ>,   cudaFuncAttributeMaxDynamicSharedMemorySize, SMEMSZ16);
    cudaFuncSetAttribute(gemmh16<EPI_ATT>,    cudaFuncAttributeMaxDynamicSharedMemorySize, SMEMSZ16);
    cudaFuncSetAttribute(gemmfc,              cudaFuncAttributeMaxDynamicSharedMemorySize, SMEMSZF);

    fp16 *qh, *kh, *vh, *wq, *wk, *wv, *wf;
    fp16 *qhh, *khh, *vhh, *vt, *ph, *at, *sc;
    cudaGetSymbolAddress((void**)&sc, g_sc);
    cudaGetSymbolAddress((void**)&qh, g_q);   cudaGetSymbolAddress((void**)&kh, g_k);
    cudaGetSymbolAddress((void**)&vh, g_v);
    cudaGetSymbolAddress((void**)&wq, g_wq);  cudaGetSymbolAddress((void**)&wk, g_wk);
    cudaGetSymbolAddress((void**)&wv, g_wv);  cudaGetSymbolAddress((void**)&wf, g_wf);
    cudaGetSymbolAddress((void**)&qhh, g_qh); cudaGetSymbolAddress((void**)&khh, g_kh);
    cudaGetSymbolAddress((void**)&vhh, g_vh); cudaGetSymbolAddress((void**)&vt, g_vt);
    cudaGetSymbolAddress((void**)&ph, g_p);   cudaGetSymbolAddress((void**)&at, g_at);

    const int NX = B_ * S_ * D_;     // 4M
    const int NW = HD_ * D_;         // 2M
    conv7_k<<<dim3(NX / 1024, 1, 7), 256>>>(in_q, in_k, in_v, w_q, w_k, w_v, w_fc,
                                            qh, kh, vh, wq, wk, wv, wf, NX, NW);

    const float SCALE = 0.044194173824159216f;   // 1/sqrt(512)

    // 1) projections (M=8192, N=4096, K=512), all three in ONE launch (z=0..2)
    const dim3 gp(HD_ / 128, (B_ * S_) / 128, 3);
    gemmh16<EPI_PROJ><<<gp, 128, SMEMSZ16>>>(qh, wq, qhh, D_, 0, 0, 1.0f,
                                             kh, vh, wk, wv, khh, vhh);

    // 1b) V transpose: (z,s,d) -> (z,d,s) so PV stays row.col
    transp_k<<<dim3(DK_ / 64, S_ / 64, B_ * H_), 256>>>(vhh, vt);

    // 2) scores (per z: M=N=1024, K=512), scaled, fp16 out
    const dim3 gs(S_ / 128, S_ / 128, B_ * H_);
    gemmh16<EPI_SCORES><<<gs, 128, SMEMSZ16>>>(qhh, khh, sc,
                                               DK_, (long long)S_ * DK_, (long long)S_ * DK_, SCALE,
                                               nullptr, nullptr, nullptr, nullptr, nullptr, nullptr);

    // 3) softmax -> fp16 P
    softmax_k<<<B_ * H_ * S_, 256>>>(sc, ph);

    // 4) P @ V (per z: M=1024, N=512, K=1024; B = V^T)
    const dim3 gv(DK_ / 128, S_ / 128, B_ * H_);
    gemmh16<EPI_ATT><<<gv, 128, SMEMSZ16>>>(ph, vt, at,
                                            S_, (long long)S_ * S_, (long long)DK_ * S_, 1.0f,
                                            nullptr, nullptr, nullptr, nullptr, nullptr, nullptr);

    // 5) fc + residual (M=8192, N=512, K=4096), fp32 accumulate
    const dim3 gf(D_ / 128, (B_ * S_) / 128, 1);
    gemmfc<<<gf, 128, SMEMSZF>>>(at, wf, out, in_q, HD_);

    // 6) LayerNorm
    ln_k<<<B_ * S_, 256>>>(out, gamma, beta);
}

// round 17
// speedup vs baseline: 1.1620x; 1.1093x over previous
#include <cuda_runtime.h>
#include <cuda_fp16.h>
#include <cstdint>
#include <cstddef>

#define B_    8
#define S_    1024
#define D_    512
#define H_    8
#define DK_   512
#define HD_   4096

typedef __half fp16;

// ---------------- scratch (device globals; no runtime alloc) ----------------
__device__ fp16  g_sc  [(size_t)B_*H_*S_*S_];         // exp(scaled scores), fp16
__device__ float g_rsum[(size_t)B_*H_*S_];            // fp32 row sums of exp

__device__ fp16 g_q  [(size_t)B_*S_*D_];
__device__ fp16 g_k  [(size_t)B_*S_*D_];
__device__ fp16 g_v  [(size_t)B_*S_*D_];
__device__ fp16 g_wq [(size_t)HD_*D_];
__device__ fp16 g_wk [(size_t)HD_*D_];
__device__ fp16 g_wv [(size_t)HD_*D_];
__device__ fp16 g_wf [(size_t)D_*HD_];

__device__ fp16 g_qh [(size_t)B_*H_*S_*DK_];
__device__ fp16 g_kh [(size_t)B_*H_*S_*DK_];
__device__ fp16 g_vh [(size_t)B_*H_*S_*DK_];          // V heads (z, s, d)
__device__ fp16 g_vt [(size_t)B_*H_*DK_*S_];          // V transposed (z, d, s)
__device__ fp16 g_at [(size_t)B_*S_*HD_];             // attention output

// ---------------- helpers ----------------
__device__ __forceinline__ uint32_t smem_u32(const void* p) {
    uint32_t a;
    asm("{ .reg .u64 t; cvta.to.shared.u64 t, %1; cvt.u32.u64 %0, t; }"
        : "=r"(a) : "l"(p));
    return a;
}
__device__ __forceinline__ void cp16(uint32_t s, const void* g) {
    asm volatile("cp.async.cg.shared.global [%0], [%1], 16;" :: "r"(s), "l"(g));
}
__device__ __forceinline__ void cp_commit() { asm volatile("cp.async.commit_group;"); }
template <int N> __device__ __forceinline__ void cp_wait() {
    asm volatile("cp.async.wait_group %0;" :: "n"(N));
}
__device__ __forceinline__ void ldsm4(uint32_t* r, uint32_t a) {
    asm volatile("ldmatrix.sync.aligned.m8n8.x4.shared.b16 {%0,%1,%2,%3}, [%4];"
                 : "=r"(r[0]), "=r"(r[1]), "=r"(r[2]), "=r"(r[3]) : "r"(a));
}
// fp32-accumulate HMMA
__device__ __forceinline__ void mma16816(float* d, const uint32_t* a, const uint32_t* b) {
    asm volatile("mma.sync.aligned.m16n8k16.row.col.f32.f16.f16.f32 "
                 "{%0,%1,%2,%3}, {%4,%5,%6,%7}, {%8,%9}, {%0,%1,%2,%3};"
                 : "+f"(d[0]), "+f"(d[1]), "+f"(d[2]), "+f"(d[3])
                 : "r"(a[0]), "r"(a[1]), "r"(a[2]), "r"(a[3]),
                   "r"(b[0]), "r"(b[1]));
}
// fp16-accumulate HMMA (2 output regs = 4 halves)
__device__ __forceinline__ void mma16816h(uint32_t* d, const uint32_t* a, const uint32_t* b) {
    asm volatile("mma.sync.aligned.m16n8k16.row.col.f16.f16.f16.f16 "
                 "{%0,%1}, {%2,%3,%4,%5}, {%6,%7}, {%0,%1};"
                 : "+r"(d[0]), "+r"(d[1])
                 : "r"(a[0]), "r"(a[1]), "r"(a[2]), "r"(a[3]),
                   "r"(b[0]), "r"(b[1]));
}
__device__ __forceinline__ uint32_t packh2(float a, float b) {
    const __half2 h = __floats2half2_rn(a, b);
    return *reinterpret_cast<const uint32_t*>(&h);
}
__device__ __forceinline__ float2 unpackh2(uint32_t w) {
    return __half22float2(*reinterpret_cast<const __half2*>(&w));
}

// 128B-row swizzle: 16B chunk c of row r -> chunk c ^ (r & 7)
__device__ __forceinline__ uint32_t swz8(int r, int c) {
    return (uint32_t)(r * 128 + ((c ^ (r & 7)) << 4));
}

enum { EPI_SCORES = 0, EPI_PROJ = 1, EPI_ATT = 2 };

// ---------------------------------------------------------------------------
// fp16-accum HMMA GEMM (proj / exp-scores / PV). CTA 128x128, 4 warps of
// 64x64, BK=64, 2-stage cp.async, 3 CTAs/SM.
//  EPI_SCORES: C = exp(scale*(A B^T)) fp16, + fp32 row-sum atomics to rsum.
//  EPI_ATT:    C = (A B^T) * (1/rsum[row]) fp16 (deferred softmax normalize).
// ---------------------------------------------------------------------------
#define STAGE_BYTES 32768     // A 16KB + B 16KB (128 rows x 128B)
#define SMEMSZ16 (2 * STAGE_BYTES)

template <int EPI>
__global__ void __launch_bounds__(128, 3)
gemmh16(const fp16* __restrict__ A0, const fp16* __restrict__ B0,
        fp16* __restrict__ Ch, float* __restrict__ rsum,
        int K, long long strideA, long long strideB, float scale,
        const fp16* __restrict__ A1, const fp16* __restrict__ A2,
        const fp16* __restrict__ B1, const fp16* __restrict__ B2,
        fp16* __restrict__ Ch1, fp16* __restrict__ Ch2)
{
    extern __shared__ __align__(128) char smem[];
    const uint32_t sb = smem_u32(smem);
    const int tid  = threadIdx.x;
    const int wid  = tid >> 5;
    const int lane = tid & 31;
    const int wm = wid & 1;
    const int wn = wid >> 1;
    const int m0 = blockIdx.y * 128;
    const int n0 = blockIdx.x * 128;
    const int z  = blockIdx.z;

    const fp16* A;
    const fp16* B;
    fp16* Chp = Ch;
    if constexpr (EPI == EPI_PROJ) {
        A   = (z == 0) ? A0 : (z == 1) ? A1 : A2;
        B   = (z == 0) ? B0 : (z == 1) ? B1 : B2;
        Chp = (z == 0) ? Ch : (z == 1) ? Ch1 : Ch2;
    } else {
        A = A0 + (size_t)z * strideA;
        B = B0 + (size_t)z * strideB;
    }

    const int NK = K >> 6;

    auto load_iter = [&](int t, int stage) {
        const uint32_t sA = sb + (uint32_t)stage * STAGE_BYTES;
        const uint32_t sB = sA + 16384;
        const int kb = t * 64;
#pragma unroll
        for (int i = 0; i < 8; i++) {
            const int chunk = i * 128 + tid;
            const int r = chunk >> 3, c = chunk & 7;
            cp16(sA + swz8(r, c), A + (size_t)(m0 + r) * K + kb + c * 8);
        }
#pragma unroll
        for (int i = 0; i < 8; i++) {
            const int chunk = i * 128 + tid;
            const int r = chunk >> 3, c = chunk & 7;
            cp16(sB + swz8(r, c), B + (size_t)(n0 + r) * K + kb + c * 8);
        }
    };

    uint32_t acc[4][8][2];
#pragma unroll
    for (int a = 0; a < 4; a++)
#pragma unroll
        for (int b = 0; b < 8; b++) { acc[a][b][0] = 0u; acc[a][b][1] = 0u; }

    load_iter(0, 0); cp_commit();

    const int g  = lane >> 3;
    const int gl = lane & 7;

    for (int i = 0; i < NK; i++) {
        cp_wait<0>();
        __syncthreads();
        if (i + 1 < NK) { load_iter(i + 1, (i + 1) & 1); cp_commit(); }

        const uint32_t sA = sb + (uint32_t)(i & 1) * STAGE_BYTES;
        const uint32_t sB = sA + 16384;

#pragma unroll
        for (int q = 0; q < 4; q++) {
            uint32_t bfr[8][2];
#pragma unroll
            for (int ni = 0; ni < 8; ni += 2) {
                uint32_t r4[4];
                const int nr = wn * 64 + ni * 8 + ((g >> 1) << 3) + gl;
                const int c  = q * 2 + (g & 1);
                ldsm4(r4, sB + swz8(nr, c));
                bfr[ni][0]     = r4[0]; bfr[ni][1]     = r4[1];
                bfr[ni + 1][0] = r4[2]; bfr[ni + 1][1] = r4[3];
            }
#pragma unroll
            for (int mi = 0; mi < 4; mi++) {
                uint32_t afr[4];
                const int mr = wm * 64 + mi * 16 + (lane & 15);
                const int c  = q * 2 + (lane >> 4);
                ldsm4(afr, sA + swz8(mr, c));
#pragma unroll
                for (int ni = 0; ni < 8; ni++)
                    mma16816h(acc[mi][ni], afr, bfr[ni]);
            }
        }
    }

    // ---------------- epilogue ----------------
    const int l4 = lane >> 2;
    const int l2 = (lane & 3) * 2;
#pragma unroll
    for (int mi = 0; mi < 4; mi++) {
#pragma unroll
        for (int h2 = 0; h2 < 2; h2++) {
            const int row = m0 + wm * 64 + mi * 16 + l4 + h2 * 8;

            if constexpr (EPI == EPI_SCORES) {
                // exp(scale * s) store + fp32 row-sum accumulation
                float psum = 0.0f;
#pragma unroll
                for (int ni = 0; ni < 8; ni++) {
                    const int col = n0 + wn * 64 + ni * 8 + l2;
                    float2 f = unpackh2(acc[mi][ni][h2]);
                    const float e0 = __expf(f.x * scale);
                    const float e1 = __expf(f.y * scale);
                    psum += e0 + e1;
                    fp16* p = Ch + (size_t)z * S_ * S_ + (size_t)row * S_ + col;
                    *reinterpret_cast<uint32_t*>(p) = packh2(e0, e1);
                }
                // reduce across the quad (lanes share this row)
                psum += __shfl_xor_sync(0xffffffffu, psum, 1);
                psum += __shfl_xor_sync(0xffffffffu, psum, 2);
                if ((lane & 3) == 0)
                    atomicAdd(&rsum[(size_t)z * S_ + row], psum);
            } else if constexpr (EPI == EPI_ATT) {
                const float inv = 1.0f / rsum[(size_t)z * S_ + row];
                const int b = z >> 3, hh = z & (H_ - 1);
#pragma unroll
                for (int ni = 0; ni < 8; ni++) {
                    const int col = n0 + wn * 64 + ni * 8 + l2;
                    float2 f = unpackh2(acc[mi][ni][h2]);
                    const size_t base = ((size_t)(b * S_ + row)) * HD_ + hh * DK_ + col;
                    *reinterpret_cast<uint32_t*>(Ch + base) = packh2(f.x * inv, f.y * inv);
                }
            } else { // EPI_PROJ
#pragma unroll
                for (int ni = 0; ni < 8; ni++) {
                    const int col = n0 + wn * 64 + ni * 8 + l2;
                    const int b = row >> 10, s = row & (S_ - 1);
                    const int hh = col >> 9, d = col & (DK_ - 1);
                    const size_t base = (((size_t)(b * H_ + hh)) * S_ + s) * DK_ + d;
                    *reinterpret_cast<uint32_t*>(Chp + base) = acc[mi][ni][h2];
                }
            }
        }
    }
}

// ---------------------------------------------------------------------------
// fp32-accum HMMA GEMM for fc (+residual). CTA 128x128, 4 warps, BK=64,
// 3-stage cp.async, 2 CTAs/SM.
// ---------------------------------------------------------------------------
#define SMEMSZF (3 * STAGE_BYTES)

__global__ void __launch_bounds__(128, 2)
gemmfc(const fp16* __restrict__ A, const fp16* __restrict__ B,
       float* __restrict__ Cf, const float* __restrict__ resid, int K)
{
    extern __shared__ __align__(128) char smem[];
    const uint32_t sb = smem_u32(smem);
    const int tid  = threadIdx.x;
    const int wid  = tid >> 5;
    const int lane = tid & 31;
    const int wm = wid & 1;
    const int wn = wid >> 1;
    const int m0 = blockIdx.y * 128;
    const int n0 = blockIdx.x * 128;

    const int NK = K >> 6;

    auto load_iter = [&](int t, int stage) {
        const uint32_t sA = sb + (uint32_t)stage * STAGE_BYTES;
        const uint32_t sB = sA + 16384;
        const int kb = t * 64;
#pragma unroll
        for (int i = 0; i < 8; i++) {
            const int chunk = i * 128 + tid;
            const int r = chunk >> 3, c = chunk & 7;
            cp16(sA + swz8(r, c), A + (size_t)(m0 + r) * K + kb + c * 8);
        }
#pragma unroll
        for (int i = 0; i < 8; i++) {
            const int chunk = i * 128 + tid;
            const int r = chunk >> 3, c = chunk & 7;
            cp16(sB + swz8(r, c), B + (size_t)(n0 + r) * K + kb + c * 8);
        }
    };

    float acc[4][8][4];
#pragma unroll
    for (int a = 0; a < 4; a++)
#pragma unroll
        for (int b = 0; b < 8; b++)
#pragma unroll
            for (int c = 0; c < 4; c++) acc[a][b][c] = 0.0f;

    load_iter(0, 0); cp_commit();
    load_iter(1, 1); cp_commit();

    const int g  = lane >> 3;
    const int gl = lane & 7;

    for (int i = 0; i < NK; i++) {
        cp_wait<1>();
        __syncthreads();
        const int j = i + 2;
        if (j < NK) load_iter(j, j % 3);
        cp_commit();

        const uint32_t sA = sb + (uint32_t)(i % 3) * STAGE_BYTES;
        const uint32_t sB = sA + 16384;

#pragma unroll
        for (int q = 0; q < 4; q++) {
            uint32_t bfr[8][2];
#pragma unroll
            for (int ni = 0; ni < 8; ni += 2) {
                uint32_t r4[4];
                const int nr = wn * 64 + ni * 8 + ((g >> 1) << 3) + gl;
                const int c  = q * 2 + (g & 1);
                ldsm4(r4, sB + swz8(nr, c));
                bfr[ni][0]     = r4[0]; bfr[ni][1]     = r4[1];
                bfr[ni + 1][0] = r4[2]; bfr[ni + 1][1] = r4[3];
            }
#pragma unroll
            for (int mi = 0; mi < 4; mi++) {
                uint32_t afr[4];
                const int mr = wm * 64 + mi * 16 + (lane & 15);
                const int c  = q * 2 + (lane >> 4);
                ldsm4(afr, sA + swz8(mr, c));
#pragma unroll
                for (int ni = 0; ni < 8; ni++)
                    mma16816(acc[mi][ni], afr, bfr[ni]);
            }
        }
    }

    const int l4 = lane >> 2;
    const int l2 = (lane & 3) * 2;
#pragma unroll
    for (int mi = 0; mi < 4; mi++) {
#pragma unroll
        for (int h2 = 0; h2 < 2; h2++) {
            const int row = m0 + wm * 64 + mi * 16 + l4 + h2 * 8;
#pragma unroll
            for (int ni = 0; ni < 8; ni++) {
                const int col = n0 + wn * 64 + ni * 8 + l2;
                const size_t base = (size_t)row * D_ + col;
                const float2 rv = *reinterpret_cast<const float2*>(resid + base);
                *reinterpret_cast<float2*>(Cf + base) =
                    make_float2(acc[mi][ni][2 * h2 + 0] + rv.x,
                                acc[mi][ni][2 * h2 + 1] + rv.y);
            }
        }
    }
}

// ---------------- fp32 -> fp16 convert: all 7 tensors in one launch ---------
__global__ void __launch_bounds__(256) conv7_k(
    const float* __restrict__ s0, const float* __restrict__ s1,
    const float* __restrict__ s2, const float* __restrict__ s3,
    const float* __restrict__ s4, const float* __restrict__ s5,
    const float* __restrict__ s6,
    fp16* __restrict__ h0, fp16* __restrict__ h1, fp16* __restrict__ h2,
    fp16* __restrict__ h3, fp16* __restrict__ h4, fp16* __restrict__ h5,
    fp16* __restrict__ h6,
    int n_big, int n_small)
{
    const int zz = blockIdx.z;
    const float* s; fp16* h; int n;
    switch (zz) {
        case 0: s = s0; h = h0; n = n_big;   break;
        case 1: s = s1; h = h1; n = n_big;   break;
        case 2: s = s2; h = h2; n = n_big;   break;
        case 3: s = s3; h = h3; n = n_small; break;
        case 4: s = s4; h = h4; n = n_small; break;
        case 5: s = s5; h = h5; n = n_small; break;
        default: s = s6; h = h6; n = n_small; break;
    }
    const int i = (blockIdx.x * 256 + threadIdx.x) * 4;
    if (i >= n) return;
    float4 v = *reinterpret_cast<const float4*>(s + i);
    *reinterpret_cast<uint2*>(h + i) = make_uint2(packh2(v.x, v.y), packh2(v.z, v.w));
}

// ---------------- V transpose: (z, s, d) -> (z, d, s), 64x64 tiles ----------
__global__ void __launch_bounds__(256) transp_k(const fp16* __restrict__ in,
                                                fp16* __restrict__ out)
{
    __shared__ fp16 t[64][72];
    const int zz = blockIdx.z;
    const int d0 = blockIdx.x * 64, s0 = blockIdx.y * 64;
    const int tid = threadIdx.x;
    const int rs = tid >> 2, cb = (tid & 3) * 16;

    const fp16* src = in + ((size_t)zz * S_ + s0 + rs) * DK_ + d0 + cb;
    *reinterpret_cast<uint4*>(&t[rs][cb])     = reinterpret_cast<const uint4*>(src)[0];
    *reinterpret_cast<uint4*>(&t[rs][cb + 8]) = reinterpret_cast<const uint4*>(src)[1];
    __syncthreads();

    fp16 buf[16];
#pragma unroll
    for (int j = 0; j < 16; j++) buf[j] = t[cb + j][rs];
    fp16* dst = out + ((size_t)zz * DK_ + d0 + rs) * S_ + s0 + cb;
    reinterpret_cast<uint4*>(dst)[0] = *reinterpret_cast<uint4*>(&buf[0]);
    reinterpret_cast<uint4*>(dst)[1] = *reinterpret_cast<uint4*>(&buf[8]);
}

// ---------------- LayerNorm (len 512), in-place ----------------
__global__ void __launch_bounds__(256) ln_k(float* __restrict__ out,
                                            const float* __restrict__ gamma,
                                            const float* __restrict__ beta)
{
    const size_t row = blockIdx.x;
    float2* p = reinterpret_cast<float2*>(out) + row * 256 + threadIdx.x;
    float2 v = *p;

    float s  = v.x + v.y;
    float ss = v.x * v.x + v.y * v.y;

    __shared__ float r1[8], r2[8];
#pragma unroll
    for (int o = 16; o; o >>= 1) {
        s  += __shfl_xor_sync(0xffffffffu, s, o);
        ss += __shfl_xor_sync(0xffffffffu, ss, o);
    }
    if ((threadIdx.x & 31) == 0) { r1[threadIdx.x >> 5] = s; r2[threadIdx.x >> 5] = ss; }
    __syncthreads();
    s = 0.0f; ss = 0.0f;
#pragma unroll
    for (int i = 0; i < 8; i++) { s += r1[i]; ss += r2[i]; }

    const float mu  = s * (1.0f / 512.0f);
    const float var = ss * (1.0f / 512.0f) - mu * mu;
    const float inv = rsqrtf(var + 1e-6f);

    const int c = threadIdx.x * 2;
    v.x = (v.x - mu) * inv * gamma[c + 0] + beta[c + 0];
    v.y = (v.y - mu) * inv * gamma[c + 1] + beta[c + 1];
    *p = v;
}

// ---------------------------------------------------------------------------
extern "C" void kernel_launch(void* const* d_in, const int* in_sizes, int n_in,
                              void* d_out, int out_size)
{
    const float* in_q  = (const float*)d_in[0];
    const float* in_k  = (const float*)d_in[1];
    const float* in_v  = (const float*)d_in[2];
    const float* w_q   = (const float*)d_in[3];
    const float* w_k   = (const float*)d_in[4];
    const float* w_v   = (const float*)d_in[5];
    const float* w_fc  = (const float*)d_in[6];
    const float* gamma = (const float*)d_in[7];
    const float* beta  = (const float*)d_in[8];
    float* out = (float*)d_out;

    cudaFuncSetAttribute(gemmh16<EPI_SCORES>, cudaFuncAttributeMaxDynamicSharedMemorySize, SMEMSZ16);
    cudaFuncSetAttribute(gemmh16<EPI_PROJ>,   cudaFuncAttributeMaxDynamicSharedMemorySize, SMEMSZ16);
    cudaFuncSetAttribute(gemmh16<EPI_ATT>,    cudaFuncAttributeMaxDynamicSharedMemorySize, SMEMSZ16);
    cudaFuncSetAttribute(gemmfc,              cudaFuncAttributeMaxDynamicSharedMemorySize, SMEMSZF);

    fp16 *qh, *kh, *vh, *wq, *wk, *wv, *wf;
    fp16 *qhh, *khh, *vhh, *vt, *at, *sc;
    float *rsum;
    cudaGetSymbolAddress((void**)&sc, g_sc);
    cudaGetSymbolAddress((void**)&rsum, g_rsum);
    cudaGetSymbolAddress((void**)&qh, g_q);   cudaGetSymbolAddress((void**)&kh, g_k);
    cudaGetSymbolAddress((void**)&vh, g_v);
    cudaGetSymbolAddress((void**)&wq, g_wq);  cudaGetSymbolAddress((void**)&wk, g_wk);
    cudaGetSymbolAddress((void**)&wv, g_wv);  cudaGetSymbolAddress((void**)&wf, g_wf);
    cudaGetSymbolAddress((void**)&qhh, g_qh); cudaGetSymbolAddress((void**)&khh, g_kh);
    cudaGetSymbolAddress((void**)&vhh, g_vh); cudaGetSymbolAddress((void**)&vt, g_vt);
    cudaGetSymbolAddress((void**)&at, g_at);

    // zero the row-sum accumulator (graph-capturable async memset)
    cudaMemsetAsync(rsum, 0, (size_t)B_ * H_ * S_ * sizeof(float));

    const int NX = B_ * S_ * D_;     // 4M
    const int NW = HD_ * D_;         // 2M
    conv7_k<<<dim3(NX / 1024, 1, 7), 256>>>(in_q, in_k, in_v, w_q, w_k, w_v, w_fc,
                                            qh, kh, vh, wq, wk, wv, wf, NX, NW);

    const float SCALE = 0.044194173824159216f;   // 1/sqrt(512)

    // 1) projections (M=8192, N=4096, K=512), all three in ONE launch (z=0..2)
    const dim3 gp(HD_ / 128, (B_ * S_) / 128, 3);
    gemmh16<EPI_PROJ><<<gp, 128, SMEMSZ16>>>(qh, wq, qhh, nullptr, D_, 0, 0, 1.0f,
                                             kh, vh, wk, wv, khh, vhh);

    // 1b) V transpose: (z,s,d) -> (z,d,s) so PV stays row.col
    transp_k<<<dim3(DK_ / 64, S_ / 64, B_ * H_), 256>>>(vhh, vt);

    // 2) exp-scores (per z: M=N=1024, K=512) + row sums (fused softmax part 1)
    const dim3 gs(S_ / 128, S_ / 128, B_ * H_);
    gemmh16<EPI_SCORES><<<gs, 128, SMEMSZ16>>>(qhh, khh, sc, rsum,
                                               DK_, (long long)S_ * DK_, (long long)S_ * DK_, SCALE,
                                               nullptr, nullptr, nullptr, nullptr, nullptr, nullptr);

    // 3) P~ @ V with deferred 1/rowsum normalization (fused softmax part 2)
    const dim3 gv(DK_ / 128, S_ / 128, B_ * H_);
    gemmh16<EPI_ATT><<<gv, 128, SMEMSZ16>>>(sc, vt, at, rsum,
                                            S_, (long long)S_ * S_, (long long)DK_ * S_, 1.0f,
                                            nullptr, nullptr, nullptr, nullptr, nullptr, nullptr);

    // 4) fc + residual (M=8192, N=512, K=4096), fp32 accumulate
    const dim3 gf(D_ / 128, (B_ * S_) / 128, 1);
    gemmfc<<<gf, 128, SMEMSZF>>>(at, wf, out, in_q, HD_);

    // 5) LayerNorm
    ln_k<<<B_ * S_, 256>>>(out, gamma, beta);
}